// round 2
// baseline (speedup 1.0000x reference)
#include <cuda_runtime.h>
#include <math.h>

#define Bz 32
#define Cc 384
#define Nn 4096
#define Mm 64
#define Rr 16
#define TN 128
#define NT_PER_CTA 2
#define NTILEGRP (Nn / TN / NT_PER_CTA)   // 16
#define LST 268      // Ls row stride (floats): conflict-free for GEMM2 B frags, 16B-aligned rows
#define XST 136      // X chunk row stride (floats): conflict-free for GEMM1 B frags
#define CHUNK 32     // c-rows per staged chunk
#define SMEM_FLOATS (CHUNK*XST + Mm*LST + 64)
#define SMEM_BYTES (SMEM_FLOATS * 4)

__device__ float g_W[Mm * Cc];   // (U @ Vw)  [64, 384]
__device__ float g_b[Mm];        // (U @ Vb)  [64]

__global__ void precompute_kernel(const float* __restrict__ Vw,
                                  const float* __restrict__ Vb,
                                  const float* __restrict__ U) {
    int t = blockIdx.x * blockDim.x + threadIdx.x;
    if (t < Mm * Cc) {
        int m = t / Cc, c = t % Cc;
        float s = 0.f;
        #pragma unroll
        for (int r = 0; r < Rr; ++r) s += U[m * Rr + r] * Vw[r * Cc + c];
        g_W[t] = s;
    }
    if (t < Mm) {
        float s = 0.f;
        #pragma unroll
        for (int r = 0; r < Rr; ++r) s += U[t * Rr + r] * Vb[r];
        g_b[t] = s;
    }
}

__global__ void zeroT_kernel(float4* outT4) {
    outT4[blockIdx.x * blockDim.x + threadIdx.x] = make_float4(0.f, 0.f, 0.f, 0.f);
}

__device__ __forceinline__ unsigned f2tf(float f) {
    unsigned u;
    asm("cvt.rna.tf32.f32 %0, %1;" : "=r"(u) : "f"(f));
    return u;
}

__device__ __forceinline__ void mma_tf32(float c[4], const unsigned a[4],
                                         unsigned b0, unsigned b1) {
    asm volatile(
        "mma.sync.aligned.m16n8k8.row.col.f32.tf32.tf32.f32 "
        "{%0,%1,%2,%3}, {%4,%5,%6,%7}, {%8,%9}, {%0,%1,%2,%3};"
        : "+f"(c[0]), "+f"(c[1]), "+f"(c[2]), "+f"(c[3])
        : "r"(a[0]), "r"(a[1]), "r"(a[2]), "r"(a[3]), "r"(b0), "r"(b1));
}

__global__ __launch_bounds__(256, 2)
void main_kernel(const float* __restrict__ x,
                 float* __restrict__ outT,
                 float* __restrict__ outS) {
    extern __shared__ float smem[];
    float* Xs   = smem;                      // [CHUNK][XST]
    float* Ls   = smem + CHUNK * XST;        // [Mm][LST] (2 tiles: col bases 0 / 136)
    float* bias = Ls + Mm * LST;             // [64]

    const int tid  = threadIdx.x;
    const int warp = tid >> 5;
    const int lane = tid & 31;
    const int g    = lane >> 2;   // mma "group" (row within fragment)
    const int tg   = lane & 3;    // thread-in-group (col within fragment)

    const int cta  = blockIdx.x;
    const int b    = cta / NTILEGRP;
    const int tIdx = cta % NTILEGRP;

    const float* xb = x + (size_t)b * Cc * Nn;

    if (tid < Mm) bias[tid] = g_b[tid];

    // GEMM1 warp tiling: warp covers m in [m0, m0+32) (2 m16 blocks), n in [nq, nq+32) (4 n8 tiles)
    const int m0 = (warp & 1) * 32;
    const int nq = (warp >> 1) * 32;

    for (int it = 0; it < NT_PER_CTA; ++it) {
        const int n0  = (tIdx * NT_PER_CTA + it) * TN;
        const int lsb = it * 136;   // Ls column base for this tile

        float acc1[2][4][4];
        #pragma unroll
        for (int mb = 0; mb < 2; ++mb)
            #pragma unroll
            for (int nt = 0; nt < 4; ++nt)
                #pragma unroll
                for (int k = 0; k < 4; ++k) acc1[mb][nt][k] = 0.f;

        // ---- GEMM1: L = W @ x_tile, streaming x through smem ----
        for (int ck = 0; ck < Cc; ck += CHUNK) {
            __syncthreads();
            #pragma unroll
            for (int i = 0; i < (CHUNK * TN / 4) / 256; ++i) {  // 4 float4 per thread
                int l4 = tid + i * 256;
                int r  = l4 >> 5;         // chunk row
                int jj = l4 & 31;         // float4 col
                float4 v = *(const float4*)(xb + (size_t)(ck + r) * Nn + n0 + jj * 4);
                *(float4*)(Xs + r * XST + jj * 4) = v;
            }
            __syncthreads();
            #pragma unroll
            for (int ks = 0; ks < CHUNK / 8; ++ks) {
                const int kc = ck + ks * 8;
                unsigned a[2][4];
                #pragma unroll
                for (int mb = 0; mb < 2; ++mb) {
                    const float* Wp = g_W + (m0 + mb * 16 + g) * Cc + kc + tg;
                    a[mb][0] = f2tf(Wp[0]);
                    a[mb][1] = f2tf(Wp[8 * Cc]);
                    a[mb][2] = f2tf(Wp[4]);
                    a[mb][3] = f2tf(Wp[8 * Cc + 4]);
                }
                #pragma unroll
                for (int nt = 0; nt < 4; ++nt) {
                    int col = nq + nt * 8 + g;
                    unsigned b0 = f2tf(Xs[(ks * 8 + tg) * XST + col]);
                    unsigned b1 = f2tf(Xs[(ks * 8 + tg + 4) * XST + col]);
                    mma_tf32(acc1[0][nt], a[0], b0, b1);
                    mma_tf32(acc1[1][nt], a[1], b0, b1);
                }
            }
        }
        __syncthreads();
        // store L fragments to Ls
        #pragma unroll
        for (int mb = 0; mb < 2; ++mb) {
            #pragma unroll
            for (int nt = 0; nt < 4; ++nt) {
                int col = lsb + nq + nt * 8 + tg * 2;
                int r0  = m0 + mb * 16 + g;
                *(float2*)(Ls + r0 * LST + col)       = make_float2(acc1[mb][nt][0], acc1[mb][nt][1]);
                *(float2*)(Ls + (r0 + 8) * LST + col) = make_float2(acc1[mb][nt][2], acc1[mb][nt][3]);
            }
        }
        __syncthreads();

        // ---- softmax over token dim (64 rows) per column ----
        if (tid < TN) {
            const int j = lsb + tid;
            float mx = -1e30f;
            #pragma unroll 8
            for (int m = 0; m < Mm; ++m) {
                float v = Ls[m * LST + j] + bias[m];
                mx = fmaxf(mx, v);
            }
            float sum = 0.f;
            #pragma unroll 8
            for (int m = 0; m < Mm; ++m) {
                float e = __expf(Ls[m * LST + j] + bias[m] - mx);
                Ls[m * LST + j] = e;
                sum += e;
            }
            float inv = __frcp_rn(sum);
            #pragma unroll 8
            for (int m = 0; m < Mm; ++m) Ls[m * LST + j] *= inv;
        }
        __syncthreads();

        // ---- write S tile (coalesced float4) ----
        float* Sb = outS + (size_t)b * Mm * Nn + n0;
        #pragma unroll
        for (int i = 0; i < (Mm * TN / 4) / 256; ++i) {  // 8 float4 per thread
            int l4 = tid + i * 256;
            int m  = l4 >> 5;
            int jj = l4 & 31;
            float4 v = *(const float4*)(Ls + m * LST + lsb + jj * 4);
            *(float4*)(Sb + (size_t)m * Nn + jj * 4) = v;
        }
    }

    // ---- GEMM2: T[c, m] += x_tile @ S_tile^T (both tiles), atomically accumulated ----
    float* Tb = outT + (size_t)b * Cc * Mm;
    for (int cbi = 0; cbi < 3; ++cbi) {
        const int c0 = (warp + cbi * 8) * 16;   // 24 m16 c-blocks over 8 warps
        float acc2[8][4];
        #pragma unroll
        for (int i = 0; i < 8; ++i) { acc2[i][0] = acc2[i][1] = acc2[i][2] = acc2[i][3] = 0.f; }

        for (int it = 0; it < NT_PER_CTA; ++it) {
            const int n0  = (tIdx * NT_PER_CTA + it) * TN;
            const int lsb = it * 136;
            #pragma unroll 4
            for (int kk = 0; kk < TN / 8; ++kk) {
                const int j0 = kk * 8;
                const float* Xp = xb + (size_t)(c0 + g) * Nn + n0 + j0 + tg;
                unsigned a[4];
                a[0] = f2tf(Xp[0]);
                a[1] = f2tf(Xp[8 * Nn]);
                a[2] = f2tf(Xp[4]);
                a[3] = f2tf(Xp[8 * Nn + 4]);
                #pragma unroll
                for (int nt = 0; nt < 8; ++nt) {
                    unsigned b0 = f2tf(Ls[(nt * 8 + g) * LST + lsb + j0 + tg]);
                    unsigned b1 = f2tf(Ls[(nt * 8 + g) * LST + lsb + j0 + tg + 4]);
                    mma_tf32(acc2[nt], a, b0, b1);
                }
            }
        }
        #pragma unroll
        for (int nt = 0; nt < 8; ++nt) {
            int col = nt * 8 + tg * 2;
            atomicAdd(&Tb[(c0 + g)     * Mm + col],     acc2[nt][0]);
            atomicAdd(&Tb[(c0 + g)     * Mm + col + 1], acc2[nt][1]);
            atomicAdd(&Tb[(c0 + g + 8) * Mm + col],     acc2[nt][2]);
            atomicAdd(&Tb[(c0 + g + 8) * Mm + col + 1], acc2[nt][3]);
        }
    }
}

extern "C" void kernel_launch(void* const* d_in, const int* in_sizes, int n_in,
                              void* d_out, int out_size) {
    const float* x  = (const float*)d_in[0];
    const float* Vw = (const float*)d_in[1];
    const float* Vb = (const float*)d_in[2];
    const float* U  = (const float*)d_in[3];

    float* out  = (float*)d_out;
    float* outT = out;                             // [B, C, M]
    float* outS = out + (size_t)Bz * Cc * Mm;      // [B, M, N]

    cudaFuncSetAttribute(main_kernel, cudaFuncAttributeMaxDynamicSharedMemorySize, SMEM_BYTES);

    precompute_kernel<<<(Mm * Cc + 255) / 256, 256>>>(Vw, Vb, U);
    zeroT_kernel<<<(Bz * Cc * Mm / 4) / 256, 256>>>((float4*)outT);
    main_kernel<<<Bz * NTILEGRP, 256, SMEM_BYTES>>>(x, outT, outS);
}

// round 3
// speedup vs baseline: 1.8119x; 1.8119x over previous
#include <cuda_runtime.h>
#include <cuda_fp16.h>

#define Bz 32
#define Cc 384
#define Nn 4096
#define Mm 64
#define TN 128
#define NT 2                    // n-tiles per CTA
#define NGRP (Nn / TN / NT)     // 16 CTAs per batch
#define WST 392                 // Ws row stride (halfs): 784B = 49*16 -> ldmatrix conflict-free
#define XSTH 136                // xh row stride (halfs): 272B = 17*16 -> conflict-free
#define SSTH 136                // Sh row stride (halfs)
#define LST 132                 // Ls row stride (floats)

// smem layout (bytes)
#define OFF_LS   0
#define OFF_BIAS (OFF_LS + Mm * LST * 4)       // 33792
#define OFF_CINV (OFF_BIAS + 64 * 4)           // 34048
#define OFF_XH   (OFF_CINV + 128 * 4)          // 34560
#define OFF_SH   (OFF_XH + Cc * XSTH * 2)      // 139008
#define OFF_WS   (OFF_SH + Mm * SSTH * 2)      // 156416
#define SMEM_BYTES (OFF_WS + Mm * WST * 2)     // 206592

__device__ __half g_Wh[Mm * Cc];   // f16(U @ Vw)
__device__ float  g_b[Mm];         // U @ Vb

__global__ void precompute_kernel(const float* __restrict__ Vw,
                                  const float* __restrict__ Vb,
                                  const float* __restrict__ U) {
    int t = blockIdx.x * blockDim.x + threadIdx.x;
    if (t < Mm * Cc) {
        int m = t / Cc, c = t % Cc;
        float s = 0.f;
        #pragma unroll
        for (int r = 0; r < 16; ++r) s += U[m * 16 + r] * Vw[r * Cc + c];
        g_Wh[t] = __float2half_rn(s);
    }
    if (t < Mm) {
        float s = 0.f;
        #pragma unroll
        for (int r = 0; r < 16; ++r) s += U[t * 16 + r] * Vb[r];
        g_b[t] = s;
    }
}

__global__ void zeroT_kernel(float4* outT4) {
    outT4[blockIdx.x * blockDim.x + threadIdx.x] = make_float4(0.f, 0.f, 0.f, 0.f);
}

__device__ __forceinline__ void ldsm_x4(unsigned r[4], unsigned saddr) {
    asm volatile("ldmatrix.sync.aligned.m8n8.x4.shared.b16 {%0,%1,%2,%3}, [%4];"
                 : "=r"(r[0]), "=r"(r[1]), "=r"(r[2]), "=r"(r[3]) : "r"(saddr));
}
__device__ __forceinline__ void ldsm_x2t(unsigned& r0, unsigned& r1, unsigned saddr) {
    asm volatile("ldmatrix.sync.aligned.m8n8.x2.trans.shared.b16 {%0,%1}, [%2];"
                 : "=r"(r0), "=r"(r1) : "r"(saddr));
}
__device__ __forceinline__ void ldsm_x2(unsigned& r0, unsigned& r1, unsigned saddr) {
    asm volatile("ldmatrix.sync.aligned.m8n8.x2.shared.b16 {%0,%1}, [%2];"
                 : "=r"(r0), "=r"(r1) : "r"(saddr));
}
__device__ __forceinline__ void mma_f16(float c[4], const unsigned a[4],
                                        unsigned b0, unsigned b1) {
    asm volatile(
        "mma.sync.aligned.m16n8k16.row.col.f32.f16.f16.f32 "
        "{%0,%1,%2,%3}, {%4,%5,%6,%7}, {%8,%9}, {%0,%1,%2,%3};"
        : "+f"(c[0]), "+f"(c[1]), "+f"(c[2]), "+f"(c[3])
        : "r"(a[0]), "r"(a[1]), "r"(a[2]), "r"(a[3]), "r"(b0), "r"(b1));
}

__global__ __launch_bounds__(256, 1)
void main_kernel(const float* __restrict__ x,
                 float* __restrict__ outT,
                 float* __restrict__ outS) {
    extern __shared__ char smem[];
    float*  Ls   = (float*)(smem + OFF_LS);
    float*  bias = (float*)(smem + OFF_BIAS);
    float*  cinv = (float*)(smem + OFF_CINV);
    __half* xh   = (__half*)(smem + OFF_XH);
    __half* Sh   = (__half*)(smem + OFF_SH);
    __half* Ws   = (__half*)(smem + OFF_WS);

    const unsigned xh_a = (unsigned)__cvta_generic_to_shared(xh);
    const unsigned sh_a = (unsigned)__cvta_generic_to_shared(Sh);
    const unsigned ws_a = (unsigned)__cvta_generic_to_shared(Ws);

    const int tid  = threadIdx.x;
    const int warp = tid >> 5;
    const int lane = tid & 31;
    const int g    = lane >> 2;
    const int t4   = lane & 3;

    const int b    = blockIdx.x >> 4;
    const int tIdx = blockIdx.x & 15;
    const float* xb = x + (size_t)b * Cc * Nn;

    // per-lane ldmatrix offsets
    const int  wrow  = (lane & 7) + ((lane >> 3) & 1) * 8;   // row within 16
    const int  wcolh = (lane >> 4) * 8;                      // col-half (x4)
    const unsigned ws_lane = ws_a + (unsigned)(wrow * WST + wcolh) * 2;
    const unsigned xb_lane = xh_a + (unsigned)((lane & 15) * XSTH) * 2;      // GEMM1 B (trans)
    const unsigned xa_lane = xh_a + (unsigned)(wrow * XSTH + wcolh) * 2;     // GEMM2 A
    const unsigned sh_lane = sh_a + (unsigned)((lane & 7) * SSTH + ((lane >> 3) & 1) * 8) * 2;

    // ---- stage W (f16) and bias into smem ----
    {
        const uint4* src = (const uint4*)g_Wh;   // 3072 uint4, rows of 48
        #pragma unroll
        for (int i = 0; i < 12; ++i) {
            int u = tid + i * 256;
            int row = u / 48, c16 = u % 48;
            *(uint4*)(Ws + row * WST + c16 * 8) = src[u];
        }
        if (tid < Mm) bias[tid] = g_b[tid];
    }

    const int nw = warp * 16;        // GEMM1 n-columns for this warp
    float acc2[3][8][4];
    #pragma unroll
    for (int i = 0; i < 3; ++i)
        #pragma unroll
        for (int j = 0; j < 8; ++j)
            #pragma unroll
            for (int k = 0; k < 4; ++k) acc2[i][j][k] = 0.f;

    for (int it = 0; it < NT; ++it) {
        const int n0 = (tIdx * NT + it) * TN;
        __syncthreads();   // protect xh/Sh reuse from previous tile

        // ---- load x tile [384 x 128] f32 -> f16 smem, fully coalesced ----
        {
            const float4* xr = (const float4*)(xb + n0);   // row stride Nn/4 float4
            #pragma unroll 4
            for (int i = 0; i < 48; ++i) {
                int row = warp + i * 8;
                float4 v = xr[(size_t)row * (Nn / 4) + lane];
                __half2 h0 = __floats2half2_rn(v.x, v.y);
                __half2 h1 = __floats2half2_rn(v.z, v.w);
                *(uint2*)(xh + row * XSTH + lane * 4) =
                    make_uint2(*(unsigned*)&h0, *(unsigned*)&h1);
            }
        }
        __syncthreads();

        // ---- GEMM1: L[64 x 128] = W @ x_tile ----
        float acc1[4][2][4];
        #pragma unroll
        for (int i = 0; i < 4; ++i)
            #pragma unroll
            for (int j = 0; j < 2; ++j)
                #pragma unroll
                for (int k = 0; k < 4; ++k) acc1[i][j][k] = 0.f;

        for (int k0 = 0; k0 < Cc; k0 += 16) {
            unsigned bf0[2], bf1[2];
            ldsm_x2t(bf0[0], bf0[1], xb_lane + (unsigned)(k0 * XSTH + nw) * 2);
            ldsm_x2t(bf1[0], bf1[1], xb_lane + (unsigned)(k0 * XSTH + nw + 8) * 2);
            #pragma unroll
            for (int mt = 0; mt < 4; ++mt) {
                unsigned a[4];
                ldsm_x4(a, ws_lane + (unsigned)(mt * 16 * WST + k0) * 2);
                mma_f16(acc1[mt][0], a, bf0[0], bf0[1]);
                mma_f16(acc1[mt][1], a, bf1[0], bf1[1]);
            }
        }
        // store L to smem (f32)
        #pragma unroll
        for (int mt = 0; mt < 4; ++mt)
            #pragma unroll
            for (int nt = 0; nt < 2; ++nt) {
                int row = mt * 16 + g;
                int col = nw + nt * 8 + t4 * 2;
                *(float2*)(Ls + row * LST + col)       = make_float2(acc1[mt][nt][0], acc1[mt][nt][1]);
                *(float2*)(Ls + (row + 8) * LST + col) = make_float2(acc1[mt][nt][2], acc1[mt][nt][3]);
            }
        __syncthreads();

        // ---- softmax over 64 tokens per column ----
        if (tid < TN) {
            const int j = tid;
            float mx = -1e30f;
            #pragma unroll 16
            for (int m = 0; m < Mm; ++m)
                mx = fmaxf(mx, Ls[m * LST + j] + bias[m]);
            float s = 0.f;
            #pragma unroll 16
            for (int m = 0; m < Mm; ++m) {
                float e = __expf(Ls[m * LST + j] + bias[m] - mx);
                Ls[m * LST + j] = e;
                s += e;
            }
            cinv[j] = __frcp_rn(s);
        }
        __syncthreads();

        // ---- write S (f32, coalesced) + build f16 copy for GEMM2 ----
        {
            float* Sb = outS + (size_t)b * Mm * Nn + n0;
            #pragma unroll
            for (int i = 0; i < 8; ++i) {
                int u = tid + i * 256;
                int m = u >> 5, c4 = u & 31;
                float4 v = *(const float4*)(Ls + m * LST + c4 * 4);
                float4 w = *(const float4*)(cinv + c4 * 4);
                v.x *= w.x; v.y *= w.y; v.z *= w.z; v.w *= w.w;
                *(float4*)(Sb + (size_t)m * Nn + c4 * 4) = v;
                __half2 h0 = __floats2half2_rn(v.x, v.y);
                __half2 h1 = __floats2half2_rn(v.z, v.w);
                *(uint2*)(Sh + m * SSTH + c4 * 4) =
                    make_uint2(*(unsigned*)&h0, *(unsigned*)&h1);
            }
        }
        __syncthreads();

        // ---- GEMM2: T[384 x 64] += x_tile @ S_tile^T  (accumulated across tiles) ----
        for (int k0 = 0; k0 < TN; k0 += 16) {
            unsigned bfr[8][2];
            #pragma unroll
            for (int nt = 0; nt < 8; ++nt)
                ldsm_x2(bfr[nt][0], bfr[nt][1],
                        sh_lane + (unsigned)(nt * 8 * SSTH + k0) * 2);
            #pragma unroll
            for (int cbi = 0; cbi < 3; ++cbi) {
                unsigned a[4];
                ldsm_x4(a, xa_lane + (unsigned)((cbi * 128 + warp * 16) * XSTH + k0) * 2);
                #pragma unroll
                for (int nt = 0; nt < 8; ++nt)
                    mma_f16(acc2[cbi][nt], a, bfr[nt][0], bfr[nt][1]);
            }
        }
    }

    // ---- accumulate T into global ----
    float* Tb = outT + (size_t)b * Cc * Mm;
    #pragma unroll
    for (int cbi = 0; cbi < 3; ++cbi)
        #pragma unroll
        for (int nt = 0; nt < 8; ++nt) {
            int row = cbi * 128 + warp * 16 + g;
            int col = nt * 8 + t4 * 2;
            float* p0 = Tb + row * Mm + col;
            float* p1 = Tb + (row + 8) * Mm + col;
            atomicAdd(p0,     acc2[cbi][nt][0]);
            atomicAdd(p0 + 1, acc2[cbi][nt][1]);
            atomicAdd(p1,     acc2[cbi][nt][2]);
            atomicAdd(p1 + 1, acc2[cbi][nt][3]);
        }
}

extern "C" void kernel_launch(void* const* d_in, const int* in_sizes, int n_in,
                              void* d_out, int out_size) {
    const float* x  = (const float*)d_in[0];
    const float* Vw = (const float*)d_in[1];
    const float* Vb = (const float*)d_in[2];
    const float* U  = (const float*)d_in[3];

    float* out  = (float*)d_out;
    float* outT = out;                          // [B, C, M]
    float* outS = out + (size_t)Bz * Cc * Mm;   // [B, M, N]

    cudaFuncSetAttribute(main_kernel, cudaFuncAttributeMaxDynamicSharedMemorySize, SMEM_BYTES);

    precompute_kernel<<<(Mm * Cc + 255) / 256, 256>>>(Vw, Vb, U);
    zeroT_kernel<<<(Bz * Cc * Mm / 4) / 256, 256>>>((float4*)outT);
    main_kernel<<<Bz * NGRP, 256, SMEM_BYTES>>>(x, outT, outS);
}

// round 5
// speedup vs baseline: 2.4823x; 1.3699x over previous
#include <cuda_runtime.h>
#include <cuda_fp16.h>

#define Bz 32
#define Cc 384
#define Nn 4096
#define Mm 64
#define TN 128
#define NT 4                    // n-tiles per CTA
#define NGRP 8                  // CTAs per batch
#define WST 392                 // Ws row stride (halfs), 784B = 49*16
#define XSTH 136                // xh row stride (halfs), 272B = 17*16
#define SSTH 136                // Sh row stride (halfs)
#define LST 132                 // Ls row stride (floats)
#define STF 132                 // stage row stride (floats)
#define STAGE_F (32 * STF)      // floats per stage buffer

// smem layout (bytes)
#define OFF_WS    0
#define OFF_XH    (OFF_WS + Mm * WST * 2)        // 50176
#define OFF_LS    (OFF_XH + Cc * XSTH * 2)       // 154624
#define OFF_STAGE (OFF_LS + Mm * LST * 4)        // 188416
#define OFF_SH    OFF_STAGE                      // overlays stage (stage dead by then)
#define OFF_BIAS  (OFF_STAGE + 2 * STAGE_F * 4)  // 222208
#define OFF_CINV  (OFF_BIAS + 64 * 4)            // 222464
#define OFF_SCR   (OFF_CINV + 128 * 4)           // 222976
#define SMEM_BYTES (OFF_SCR + 256 * 4)           // 224000

__device__ __half g_Wh[Mm * Cc];                     // f16(U @ Vw)
__device__ float  g_b[Mm];                           // U @ Vb
__device__ float  g_part[(size_t)Bz * NGRP * Cc * Mm];  // per-CTA T partials (25 MB)

__global__ void precompute_kernel(const float* __restrict__ Vw,
                                  const float* __restrict__ Vb,
                                  const float* __restrict__ U) {
    int t = blockIdx.x * blockDim.x + threadIdx.x;
    if (t < Mm * Cc) {
        int m = t / Cc, c = t % Cc;
        float s = 0.f;
        #pragma unroll
        for (int r = 0; r < 16; ++r) s += U[m * 16 + r] * Vw[r * Cc + c];
        g_Wh[t] = __float2half_rn(s);
    }
    if (t < Mm) {
        float s = 0.f;
        #pragma unroll
        for (int r = 0; r < 16; ++r) s += U[t * 16 + r] * Vb[r];
        g_b[t] = s;
    }
}

__global__ void reduceT_kernel(float4* __restrict__ outT4) {
    const int Q = Cc * Mm / 4;                      // 6144 float4 per partial
    int i = blockIdx.x * blockDim.x + threadIdx.x;  // over Bz*Q = 196608
    int b = i / Q, r = i % Q;
    const float4* p = (const float4*)g_part + (size_t)b * NGRP * Q + r;
    float4 s = make_float4(0.f, 0.f, 0.f, 0.f);
    #pragma unroll
    for (int k = 0; k < NGRP; ++k) {
        float4 v = p[(size_t)k * Q];
        s.x += v.x; s.y += v.y; s.z += v.z; s.w += v.w;
    }
    outT4[i] = s;
}

__device__ __forceinline__ void ldsm_x4(unsigned r[4], unsigned saddr) {
    asm volatile("ldmatrix.sync.aligned.m8n8.x4.shared.b16 {%0,%1,%2,%3}, [%4];"
                 : "=r"(r[0]), "=r"(r[1]), "=r"(r[2]), "=r"(r[3]) : "r"(saddr));
}
__device__ __forceinline__ void ldsm_x2t(unsigned& r0, unsigned& r1, unsigned saddr) {
    asm volatile("ldmatrix.sync.aligned.m8n8.x2.trans.shared.b16 {%0,%1}, [%2];"
                 : "=r"(r0), "=r"(r1) : "r"(saddr));
}
__device__ __forceinline__ void ldsm_x2(unsigned& r0, unsigned& r1, unsigned saddr) {
    asm volatile("ldmatrix.sync.aligned.m8n8.x2.shared.b16 {%0,%1}, [%2];"
                 : "=r"(r0), "=r"(r1) : "r"(saddr));
}
__device__ __forceinline__ void mma_f16(float c[4], const unsigned a[4],
                                        unsigned b0, unsigned b1) {
    asm volatile(
        "mma.sync.aligned.m16n8k16.row.col.f32.f16.f16.f32 "
        "{%0,%1,%2,%3}, {%4,%5,%6,%7}, {%8,%9}, {%0,%1,%2,%3};"
        : "+f"(c[0]), "+f"(c[1]), "+f"(c[2]), "+f"(c[3])
        : "r"(a[0]), "r"(a[1]), "r"(a[2]), "r"(a[3]), "r"(b0), "r"(b1));
}
__device__ __forceinline__ void cp16(unsigned sdst, const void* gsrc) {
    asm volatile("cp.async.cg.shared.global [%0], [%1], 16;" :: "r"(sdst), "l"(gsrc));
}

__global__ __launch_bounds__(256, 1)
void main_kernel(const float* __restrict__ x,
                 float* __restrict__ outS) {
    extern __shared__ char smem[];
    __half* Ws    = (__half*)(smem + OFF_WS);
    __half* xh    = (__half*)(smem + OFF_XH);
    float*  Ls    = (float*)(smem + OFF_LS);
    float*  stage = (float*)(smem + OFF_STAGE);
    __half* Sh    = (__half*)(smem + OFF_SH);
    float*  bias  = (float*)(smem + OFF_BIAS);
    float*  cinv  = (float*)(smem + OFF_CINV);
    float*  scr   = (float*)(smem + OFF_SCR);

    const unsigned xh_a = (unsigned)__cvta_generic_to_shared(xh);
    const unsigned sh_a = (unsigned)__cvta_generic_to_shared(Sh);
    const unsigned ws_a = (unsigned)__cvta_generic_to_shared(Ws);
    const unsigned st_a = (unsigned)__cvta_generic_to_shared(stage);

    const int tid  = threadIdx.x;
    const int warp = tid >> 5;
    const int lane = tid & 31;
    const int g    = lane >> 2;
    const int t4   = lane & 3;

    const int b    = blockIdx.x >> 3;
    const int tIdx = blockIdx.x & 7;
    const float* xb = x + (size_t)b * Cc * Nn;

    // per-lane ldmatrix offsets (identical to the proven R2 layout)
    const int wrow  = (lane & 7) + ((lane >> 3) & 1) * 8;
    const int wcolh = (lane >> 4) * 8;
    const unsigned ws_lane = ws_a + (unsigned)(wrow * WST + wcolh) * 2;
    const unsigned xb_lane = xh_a + (unsigned)((lane & 15) * XSTH) * 2;      // GEMM1 B (trans)
    const unsigned xa_lane = xh_a + (unsigned)(wrow * XSTH + wcolh) * 2;     // GEMM2 A
    const unsigned sh_lane = sh_a + (unsigned)((lane & 7) * SSTH + ((lane >> 3) & 1) * 8) * 2;

    // stage/convert per-thread coords: 4 float4 per thread per 32x128 chunk
    const int srow = tid >> 6;        // +8 per i  -> rows 0..31
    const int sc4  = tid & 63;        // hmm 64 > 32 — use u-decomposition instead below

    // ---- stage W (f16) and bias ----
    {
        const uint4* src = (const uint4*)g_Wh;     // 3072 uint4, 48 per row
        #pragma unroll
        for (int i = 0; i < 12; ++i) {
            int u = tid + i * 256;
            int row = u / 48, c16 = u % 48;
            *(uint4*)(Ws + row * WST + c16 * 8) = src[u];
        }
        if (tid < Mm) bias[tid] = g_b[tid];
    }

    const int nw = warp * 16;
    float acc2[3][8][4];
    #pragma unroll
    for (int i = 0; i < 3; ++i)
        #pragma unroll
        for (int j = 0; j < 8; ++j)
            #pragma unroll
            for (int k = 0; k < 4; ++k) acc2[i][j][k] = 0.f;

    for (int it = 0; it < NT; ++it) {
        const int n0 = (tIdx * NT + it) * TN;
        __syncthreads();   // xh/Sh/stage reuse guard (also orders GEMM2 reads before new stage writes)

        // prefetch chunk 0 (rows 0..31)
        {
            #pragma unroll
            for (int i = 0; i < 4; ++i) {
                int u = tid + i * 256;
                int r = u >> 5, c4 = u & 31;
                cp16(st_a + (unsigned)(r * STF + c4 * 4) * 4,
                     xb + (size_t)r * Nn + n0 + c4 * 4);
            }
            asm volatile("cp.async.commit_group;");
        }

        float acc1[4][2][4];
        #pragma unroll
        for (int i = 0; i < 4; ++i)
            #pragma unroll
            for (int j = 0; j < 2; ++j)
                #pragma unroll
                for (int k = 0; k < 4; ++k) acc1[i][j][k] = 0.f;

        for (int ck = 0; ck < 12; ++ck) {
            const int buf = ck & 1;
            if (ck < 11) {   // issue next chunk
                const int nb = (ck + 1) & 1;
                const float* src = xb + (size_t)((ck + 1) * 32) * Nn + n0;
                #pragma unroll
                for (int i = 0; i < 4; ++i) {
                    int u = tid + i * 256;
                    int r = u >> 5, c4 = u & 31;
                    cp16(st_a + (unsigned)(nb * STAGE_F + r * STF + c4 * 4) * 4,
                         src + (size_t)r * Nn + c4 * 4);
                }
                asm volatile("cp.async.commit_group;");
                asm volatile("cp.async.wait_group 1;");
            } else {
                asm volatile("cp.async.wait_group 0;");
            }
            __syncthreads();

            // convert stage f32 -> xh f16 (rows ck*32 .. +32)
            {
                const float* sb = stage + buf * STAGE_F;
                #pragma unroll
                for (int i = 0; i < 4; ++i) {
                    int u = tid + i * 256;
                    int r = u >> 5, c4 = u & 31;
                    float4 v = *(const float4*)(sb + r * STF + c4 * 4);
                    __half2 h0 = __floats2half2_rn(v.x, v.y);
                    __half2 h1 = __floats2half2_rn(v.z, v.w);
                    *(uint2*)(xh + (ck * 32 + r) * XSTH + c4 * 4) =
                        make_uint2(*(unsigned*)&h0, *(unsigned*)&h1);
                }
            }
            __syncthreads();

            // GEMM1 on these 32 k-rows (2 k16 steps)
            #pragma unroll
            for (int ks = 0; ks < 2; ++ks) {
                const int k0 = ck * 32 + ks * 16;
                unsigned bf0[2], bf1[2];
                ldsm_x2t(bf0[0], bf0[1], xb_lane + (unsigned)(k0 * XSTH + nw) * 2);
                ldsm_x2t(bf1[0], bf1[1], xb_lane + (unsigned)(k0 * XSTH + nw + 8) * 2);
                #pragma unroll
                for (int mt = 0; mt < 4; ++mt) {
                    unsigned a[4];
                    ldsm_x4(a, ws_lane + (unsigned)(mt * 16 * WST + k0) * 2);
                    mma_f16(acc1[mt][0], a, bf0[0], bf0[1]);
                    mma_f16(acc1[mt][1], a, bf1[0], bf1[1]);
                }
            }
        }

        // store L (+bias) to smem
        #pragma unroll
        for (int mt = 0; mt < 4; ++mt)
            #pragma unroll
            for (int nt = 0; nt < 2; ++nt) {
                int row = mt * 16 + g;
                int col = nw + nt * 8 + t4 * 2;
                float b0 = bias[row], b1 = bias[row + 8];
                *(float2*)(Ls + row * LST + col) =
                    make_float2(acc1[mt][nt][0] + b0, acc1[mt][nt][1] + b0);
                *(float2*)(Ls + (row + 8) * LST + col) =
                    make_float2(acc1[mt][nt][2] + b1, acc1[mt][nt][3] + b1);
            }
        __syncthreads();

        // ---- softmax over 64 tokens per column, all 256 threads ----
        {
            const int j = tid & 127, h = tid >> 7;
            const int m0 = h * 32;
            float mx = -1e30f;
            #pragma unroll 8
            for (int m = m0; m < m0 + 32; ++m)
                mx = fmaxf(mx, Ls[m * LST + j]);
            scr[h * 128 + j] = mx;
            __syncthreads();
            mx = fmaxf(scr[j], scr[128 + j]);
            __syncthreads();
            float s = 0.f;
            #pragma unroll 8
            for (int m = m0; m < m0 + 32; ++m) {
                float e = __expf(Ls[m * LST + j] - mx);
                Ls[m * LST + j] = e;
                s += e;
            }
            scr[h * 128 + j] = s;
            __syncthreads();
            if (h == 0) cinv[j] = __frcp_rn(scr[j] + scr[128 + j]);
        }
        __syncthreads();

        // ---- write S (f32) + build f16 copy (Sh overlays dead stage) ----
        {
            float* Sb = outS + (size_t)b * Mm * Nn + n0;
            #pragma unroll
            for (int i = 0; i < 8; ++i) {
                int u = tid + i * 256;
                int m = u >> 5, c4 = u & 31;
                float4 v = *(const float4*)(Ls + m * LST + c4 * 4);
                float4 w = *(const float4*)(cinv + c4 * 4);
                v.x *= w.x; v.y *= w.y; v.z *= w.z; v.w *= w.w;
                *(float4*)(Sb + (size_t)m * Nn + c4 * 4) = v;
                __half2 h0 = __floats2half2_rn(v.x, v.y);
                __half2 h1 = __floats2half2_rn(v.z, v.w);
                *(uint2*)(Sh + m * SSTH + c4 * 4) =
                    make_uint2(*(unsigned*)&h0, *(unsigned*)&h1);
            }
        }
        __syncthreads();

        // ---- GEMM2: T partial += x_tile @ S_tile^T ----
        for (int k0 = 0; k0 < TN; k0 += 16) {
            unsigned bfr[8][2];
            #pragma unroll
            for (int nt = 0; nt < 8; ++nt)
                ldsm_x2(bfr[nt][0], bfr[nt][1],
                        sh_lane + (unsigned)(nt * 8 * SSTH + k0) * 2);
            #pragma unroll
            for (int cbi = 0; cbi < 3; ++cbi) {
                unsigned a[4];
                ldsm_x4(a, xa_lane + (unsigned)((cbi * 128 + warp * 16) * XSTH + k0) * 2);
                #pragma unroll
                for (int nt = 0; nt < 8; ++nt)
                    mma_f16(acc2[cbi][nt], a, bfr[nt][0], bfr[nt][1]);
            }
        }
    }

    // ---- write T partials (plain STG, no atomics) ----
    {
        float* Pb = g_part + (size_t)(b * NGRP + tIdx) * (Cc * Mm);
        #pragma unroll
        for (int cbi = 0; cbi < 3; ++cbi)
            #pragma unroll
            for (int nt = 0; nt < 8; ++nt) {
                int row = cbi * 128 + warp * 16 + g;
                int col = nt * 8 + t4 * 2;
                *(float2*)(Pb + row * Mm + col) =
                    make_float2(acc2[cbi][nt][0], acc2[cbi][nt][1]);
                *(float2*)(Pb + (row + 8) * Mm + col) =
                    make_float2(acc2[cbi][nt][2], acc2[cbi][nt][3]);
            }
    }
}

extern "C" void kernel_launch(void* const* d_in, const int* in_sizes, int n_in,
                              void* d_out, int out_size) {
    const float* x  = (const float*)d_in[0];
    const float* Vw = (const float*)d_in[1];
    const float* Vb = (const float*)d_in[2];
    const float* U  = (const float*)d_in[3];

    float* out  = (float*)d_out;
    float* outT = out;                          // [B, C, M]
    float* outS = out + (size_t)Bz * Cc * Mm;   // [B, M, N]

    cudaFuncSetAttribute(main_kernel, cudaFuncAttributeMaxDynamicSharedMemorySize, SMEM_BYTES);

    precompute_kernel<<<(Mm * Cc + 255) / 256, 256>>>(Vw, Vb, U);
    main_kernel<<<Bz * NGRP, 256, SMEM_BYTES>>>(x, outS);
    reduceT_kernel<<<(Bz * Cc * Mm / 4) / 256, 256>>>((float4*)outT);
}